// round 12
// baseline (speedup 1.0000x reference)
#include <cuda_runtime.h>
#include <cuda_bf16.h>
#include <cuda_pipeline.h>
#include <mma.h>

using namespace nvcuda;

// Problem constants
#define TT 512
#define BB 64
#define EE 512
#define HH 1024
#define G3 3072      // 3 gates * H, gate order: g, i, o
#define NCTA_REC 128 // persistent recurrence grid (64 h-tiles x 2 n-halves)

#define WS_LD 1032   // padded K stride for weight smem (conflict-free ldmatrix)
#define BS_LD 32     // carry smem batch stride (no pad; 2-way LDSM conflict accepted)
#define NBUF 3       // carry staging buffers (prefetch depth 2)
#define SMEM_WS (48 * WS_LD)            // elements per (hi|lo) weight matrix
// bytes: weights 2*2*48*1032*2 = 198144
//        Bs      3*2*64*32*2   =  24576
//        Ps      3*16*32*4     =   6144   (Hs aliases Bs)
#define SMEM_REC_BYTES (198144 + 24576 + 6144)   // 228864 <= 227KB limit

// ---------------------------------------------------------------------------
// Static device scratch (allocation-free rule: __device__ globals)
// ---------------------------------------------------------------------------
__device__ __align__(16) float         g_xz[(size_t)TT * G3 * BB];       // preactivations [T][3H][B]
__device__ __align__(16) __nv_bfloat16 g_xt_hi[(size_t)TT * EE * BB];    // embeds transposed [T][E][B]
__device__ __align__(16) __nv_bfloat16 g_xt_lo[(size_t)TT * EE * BB];
__device__ __align__(16) __nv_bfloat16 g_wx_hi[(size_t)G3 * EE];         // [3H][E] gate-major
__device__ __align__(16) __nv_bfloat16 g_wx_lo[(size_t)G3 * EE];
__device__ __align__(16) __nv_bfloat16 g_wh_hi[(size_t)G3 * HH];         // [3H][H] gate-major
__device__ __align__(16) __nv_bfloat16 g_wh_lo[(size_t)G3 * HH];
__device__ __align__(16) __nv_bfloat16 g_c_hi[2][(size_t)HH * BB];       // ping-pong carry c (bf16 hi/lo)
__device__ __align__(16) __nv_bfloat16 g_c_lo[2][(size_t)HH * BB];

// grid-barrier state (zero-initialized; g_bar_cnt returns to 0 after every barrier)
__device__ unsigned g_bar_cnt;
__device__ unsigned g_bar_gen;

// ---------------------------------------------------------------------------
// Device-wide sense-reversing barrier (all NCTA_REC CTAs co-resident, 1/SM)
// ---------------------------------------------------------------------------
__device__ __forceinline__ void grid_bar()
{
    __syncthreads();
    if (threadIdx.x == 0) {
        __threadfence();                                   // release our c writes
        unsigned gen = atomicAdd(&g_bar_gen, 0u);          // read current generation
        __threadfence();
        if (atomicAdd(&g_bar_cnt, 1u) == NCTA_REC - 1u) {
            atomicExch(&g_bar_cnt, 0u);
            __threadfence();
            atomicAdd(&g_bar_gen, 1u);                     // release everyone
        } else {
            while (atomicAdd(&g_bar_gen, 0u) == gen) __nanosleep(64);
        }
        __threadfence();                                   // acquire others' c writes
    }
    __syncthreads();
}

// ---------------------------------------------------------------------------
// Fused split: all 6 weight matrices fp32 -> bf16 hi/lo, gate-major [g; i; o]
// ---------------------------------------------------------------------------
__global__ void split6_kernel(const float* __restrict__ Wgx, const float* __restrict__ Wix,
                              const float* __restrict__ Wox, const float* __restrict__ Wgh,
                              const float* __restrict__ Wih, const float* __restrict__ Woh,
                              __nv_bfloat16* __restrict__ wx_hi, __nv_bfloat16* __restrict__ wx_lo,
                              __nv_bfloat16* __restrict__ wh_hi, __nv_bfloat16* __restrict__ wh_lo)
{
    long i = (long)blockIdx.x * blockDim.x + threadIdx.x;
    const long nWx = (long)HH * EE, nWh = (long)HH * HH;
    float v;
    __nv_bfloat16 *hi, *lo;
    long idx;
    if (i < 3 * nWx) {
        int g = (int)(i / nWx);
        long j = i - (long)g * nWx;
        const float* src = (g == 0) ? Wgx : (g == 1) ? Wix : Wox;
        v = src[j]; hi = wx_hi; lo = wx_lo; idx = i;
    } else {
        long k = i - 3 * nWx;
        if (k >= 3 * nWh) return;
        int g = (int)(k / nWh);
        long j = k - (long)g * nWh;
        const float* src = (g == 0) ? Wgh : (g == 1) ? Wih : Woh;
        v = src[j]; hi = wh_hi; lo = wh_lo; idx = k;
    }
    __nv_bfloat16 h = __float2bfloat16(v);
    hi[idx] = h;
    lo[idx] = __float2bfloat16(v - __bfloat162float(h));
}

// embeds [T][B][E] -> transposed split [T][E][B]
__global__ void transpose_split_kernel(const float* __restrict__ emb,
                                       __nv_bfloat16* __restrict__ hi,
                                       __nv_bfloat16* __restrict__ lo)
{
    long i = (long)blockIdx.x * blockDim.x + threadIdx.x;   // over T*E*B
    if (i < (long)TT * EE * BB) {
        int  b  = (int)(i & (BB - 1));
        long te = i >> 6;
        int  e  = (int)(te & (EE - 1));
        int  t  = (int)(te >> 9);
        float v = emb[((long)t * BB + b) * EE + e];
        __nv_bfloat16 h = __float2bfloat16(v);
        hi[i] = h;
        lo[i] = __float2bfloat16(v - __bfloat162float(h));
    }
}

// ---------------------------------------------------------------------------
// Phase 1: split-bf16 WMMA GEMM over all timesteps
//   C[t] = Wx[3072,512] * X[t][512,64], fp32 out.
// ---------------------------------------------------------------------------
__global__ __launch_bounds__(64)
void gemm_split_kernel(const __nv_bfloat16* __restrict__ Ah,
                       const __nv_bfloat16* __restrict__ Al,
                       const __nv_bfloat16* __restrict__ Bh_base,
                       const __nv_bfloat16* __restrict__ Bl_base,
                       float* __restrict__ C_base,
                       int K)
{
    const int m0 = blockIdx.x * 32;
    const long y = blockIdx.y;
    const __nv_bfloat16* Bh = Bh_base + y * K * 64;
    const __nv_bfloat16* Bl = Bl_base + y * K * 64;
    float* C = C_base + y * (long)G3 * 64;

    __shared__ __align__(16) __nv_bfloat16 As[2][32][16];
    __shared__ __align__(16) __nv_bfloat16 Bs[2][16][64];

    const int tid  = threadIdx.x;
    const int warp = tid >> 5;

    wmma::fragment<wmma::accumulator, 16, 16, 16, float> acc[4];
#pragma unroll
    for (int i = 0; i < 4; i++) wmma::fill_fragment(acc[i], 0.0f);

    for (int kc = 0; kc < K; kc += 16) {
        {
            int r  = tid >> 1;
            int h8 = (tid & 1) * 8;
            size_t off = (size_t)(m0 + r) * K + kc + h8;
            *(uint4*)&As[0][r][h8] = *(const uint4*)&Ah[off];
            *(uint4*)&As[1][r][h8] = *(const uint4*)&Al[off];
        }
#pragma unroll
        for (int u = tid; u < 128; u += 64) {
            int r  = u >> 3;
            int c8 = (u & 7) * 8;
            size_t off = (size_t)(kc + r) * 64 + c8;
            *(uint4*)&Bs[0][r][c8] = *(const uint4*)&Bh[off];
            *(uint4*)&Bs[1][r][c8] = *(const uint4*)&Bl[off];
        }
        __syncthreads();

        wmma::fragment<wmma::matrix_a, 16, 16, 16, __nv_bfloat16, wmma::row_major> a_hi, a_lo;
        wmma::load_matrix_sync(a_hi, &As[0][warp * 16][0], 16);
        wmma::load_matrix_sync(a_lo, &As[1][warp * 16][0], 16);
#pragma unroll
        for (int nf = 0; nf < 4; nf++) {
            wmma::fragment<wmma::matrix_b, 16, 16, 16, __nv_bfloat16, wmma::row_major> b_hi, b_lo;
            wmma::load_matrix_sync(b_hi, &Bs[0][0][nf * 16], 64);
            wmma::load_matrix_sync(b_lo, &Bs[1][0][nf * 16], 64);
            wmma::mma_sync(acc[nf], a_hi, b_hi, acc[nf]);
            wmma::mma_sync(acc[nf], a_hi, b_lo, acc[nf]);
            wmma::mma_sync(acc[nf], a_lo, b_hi, acc[nf]);
        }
        __syncthreads();
    }

#pragma unroll
    for (int nf = 0; nf < 4; nf++)
        wmma::store_matrix_sync(&C[(size_t)(m0 + warp * 16) * 64 + nf * 16],
                                acc[nf], 64, wmma::mem_row_major);
}

// ---------------------------------------------------------------------------
// Phase 2: persistent recurrence. 128 CTAs x 384 threads (12 warps).
//   warp = (gate 0-2, khalf 0-1, nf 0-1): 16 h-rows x 16 b-cols, K split by
//   kk-groups within each 64-row chunk. 3 independent accumulators per warp
//   (hi*hi, hi*lo, lo*hi) break the HMMA dependency chain. 3-buffer cp.async
//   staging with ONE __syncthreads per chunk (prefetch depth 2).
// ---------------------------------------------------------------------------
__global__ __launch_bounds__(384)
void recurrence_kernel(const __nv_bfloat16* __restrict__ Wh_hi,
                       const __nv_bfloat16* __restrict__ Wh_lo,
                       const float* __restrict__ xz,
                       const float* __restrict__ bg,
                       const float* __restrict__ bi,
                       const float* __restrict__ bo,
                       __nv_bfloat16* __restrict__ c_hi,   // [2][H*B]
                       __nv_bfloat16* __restrict__ c_lo,   // [2][H*B]
                       float* __restrict__ out)
{
    extern __shared__ __align__(128) char smem_raw[];
    __nv_bfloat16* ws_hi = (__nv_bfloat16*)smem_raw;        // [48][WS_LD]
    __nv_bfloat16* ws_lo = ws_hi + SMEM_WS;
    __nv_bfloat16* bs    = ws_lo + SMEM_WS;                 // [NBUF][2 mat][64][BS_LD]
    float* Ps = (float*)(bs + NBUF * 2 * 64 * BS_LD);       // [3][16][32]
    float* Hs = (float*)bs;                                  // alias: free at combine time

    const int cta   = blockIdx.x;
    const int h0    = (cta >> 1) * 16;    // h-tile base
    const int n0    = (cta & 1) * 32;     // batch-half base
    const int tid   = threadIdx.x;
    const int warp  = tid >> 5;           // 0..11
    const int nf    = warp & 1;           // 0..1  (16-col b fragment)
    const int khalf = (warp >> 1) & 1;    // 0..1  (kk groups 0,1 vs 2,3)
    const int gate  = warp >> 2;          // 0..2

    // ---- one-time: preload this CTA's 48x1024 hi/lo weight rows into smem
    for (int u = tid; u < 2 * 48 * 128; u += 384) {
        int m  = (u >= 6144);
        int v  = m ? u - 6144 : u;
        int r  = v >> 7;                  // local row 0..47 (= gate*16 + hl)
        int c8 = (v & 127) * 8;           // element col
        int g  = r >> 4, hl = r & 15;
        const __nv_bfloat16* src = (m ? Wh_lo : Wh_hi) + (size_t)(g * HH + h0 + hl) * HH + c8;
        __nv_bfloat16* dst = (m ? ws_lo : ws_hi) + r * WS_LD + c8;
        *(uint4*)dst = *(const uint4*)src;
    }

    // ---- one-time: zero owned slice of carry buffer 0
    for (int u = tid; u < 512; u += 384) {
        int hl = u >> 5, bl = u & 31;
        size_t off = (size_t)(h0 + hl) * BB + n0 + bl;
        c_hi[off] = __float2bfloat16(0.0f);
        c_lo[off] = __float2bfloat16(0.0f);
    }
    grid_bar();   // also publishes smem weight preload (via its __syncthreads)

    // cp.async stage of one 64-row K chunk of the carry (hi+lo), 16B chunks (.cg)
    auto stage = [&](const __nv_bfloat16* Ch, const __nv_bfloat16* Cl, int kc, int buf) {
        __nv_bfloat16* bh  = bs + (buf * 2 + 0) * 64 * BS_LD;
        __nv_bfloat16* blo = bs + (buf * 2 + 1) * 64 * BS_LD;
        for (int u = tid; u < 512; u += 384) {
            int m  = u >> 8;              // 0 = hi, 1 = lo
            int v  = u & 255;
            int r  = v >> 2;              // 0..63
            int c8 = (v & 3) * 8;         // element col 0,8,16,24
            const __nv_bfloat16* src = (m ? Cl : Ch) + (size_t)(kc + r) * BB + n0 + c8;
            __nv_bfloat16* dst = (m ? blo : bh) + r * BS_LD + c8;
            __pipeline_memcpy_async(dst, src, 16);   // cp.async.cg (L1 bypass)
        }
    };

    const __nv_bfloat16* arow_hi = ws_hi + gate * 16 * WS_LD;
    const __nv_bfloat16* arow_lo = ws_lo + gate * 16 * WS_LD;

    // combine-position ownership (<=2 positions per thread)
    const int i0 = tid, i1 = tid + 384;   // i1 < 512 only for tid < 128

    for (int t = 0; t < TT; t++) {
        const int rb = t & 1;
        const __nv_bfloat16* Ch = c_hi + (size_t)rb * HH * BB;
        const __nv_bfloat16* Cl = c_lo + (size_t)rb * HH * BB;
        __nv_bfloat16* Wch = c_hi + (size_t)(rb ^ 1) * HH * BB;
        __nv_bfloat16* Wcl = c_lo + (size_t)(rb ^ 1) * HH * BB;
        const float* xzt = xz + (size_t)t * G3 * BB;

        // prefetch xz operands for this thread's combine positions into registers
        float xzv[2][3];
        {
            int hl = i0 >> 5, bl = i0 & 31;
            int h = h0 + hl, b = n0 + bl;
#pragma unroll
            for (int g = 0; g < 3; g++)
                xzv[0][g] = __ldcg(&xzt[(size_t)(g * HH + h) * BB + b]);
            if (i1 < 512) {
                int hl1 = i1 >> 5, bl1 = i1 & 31;
                int h1 = h0 + hl1, b1 = n0 + bl1;
#pragma unroll
                for (int g = 0; g < 3; g++)
                    xzv[1][g] = __ldcg(&xzt[(size_t)(g * HH + h1) * BB + b1]);
            }
        }

        wmma::fragment<wmma::accumulator, 16, 16, 16, float> acc0, acc1, acc2;
        wmma::fill_fragment(acc0, 0.0f);
        wmma::fill_fragment(acc1, 0.0f);
        wmma::fill_fragment(acc2, 0.0f);

        stage(Ch, Cl, 0, 0);  __pipeline_commit();
        stage(Ch, Cl, 64, 1); __pipeline_commit();

        for (int kci = 0; kci < 16; kci++) {
            const int buf = kci % NBUF;
            __pipeline_wait_prior(1);     // chunk kci's group complete (thread-local)
            __syncthreads();              // publish chunk kci; MMA(kci-1) done by all
            if (kci + 2 < 16) {
                stage(Ch, Cl, (kci + 2) * 64, (kci + 2) % NBUF);
                __pipeline_commit();
            }

            const __nv_bfloat16* bhp = bs + (buf * 2 + 0) * 64 * BS_LD + nf * 16;
            const __nv_bfloat16* blp = bs + (buf * 2 + 1) * 64 * BS_LD + nf * 16;
#pragma unroll
            for (int j = 0; j < 2; j++) {
                const int kk = khalf * 2 + j;
                wmma::fragment<wmma::matrix_a, 16, 16, 16, __nv_bfloat16, wmma::row_major> a_hi, a_lo;
                wmma::load_matrix_sync(a_hi, arow_hi + kci * 64 + kk * 16, WS_LD);
                wmma::load_matrix_sync(a_lo, arow_lo + kci * 64 + kk * 16, WS_LD);
                wmma::fragment<wmma::matrix_b, 16, 16, 16, __nv_bfloat16, wmma::row_major> b_hi, b_lo;
                wmma::load_matrix_sync(b_hi, bhp + kk * 16 * BS_LD, BS_LD);
                wmma::load_matrix_sync(b_lo, blp + kk * 16 * BS_LD, BS_LD);
                wmma::mma_sync(acc0, a_hi, b_hi, acc0);   // 3 independent chains
                wmma::mma_sync(acc1, a_hi, b_lo, acc1);
                wmma::mma_sync(acc2, a_lo, b_hi, acc2);
            }
        }

        // fold the 3 partial accumulators
#pragma unroll
        for (int e = 0; e < acc0.num_elements; e++)
            acc0.x[e] += acc1.x[e] + acc2.x[e];

        // merge k-halves via Ps: khalf1 stores, khalf0 accumulates on top
        __syncthreads();                  // all MMA reads of bs done (Hs alias safe later)
        if (khalf == 1)
            wmma::store_matrix_sync(Ps + gate * 512 + nf * 16, acc0, 32, wmma::mem_row_major);
        __syncthreads();
        if (khalf == 0) {
            wmma::fragment<wmma::accumulator, 16, 16, 16, float> accP;
            wmma::load_matrix_sync(accP, Ps + gate * 512 + nf * 16, 32, wmma::mem_row_major);
#pragma unroll
            for (int e = 0; e < acc0.num_elements; e++)
                acc0.x[e] += accP.x[e];
            wmma::store_matrix_sync(Ps + gate * 512 + nf * 16, acc0, 32, wmma::mem_row_major);
        }
        __syncthreads();

        // combine for this CTA's 16x32 block (xz already in registers)
#pragma unroll
        for (int q = 0; q < 2; q++) {
            int i = (q == 0) ? i0 : i1;
            if (i < 512) {
                int hl = i >> 5, bl = i & 31;
                int h = h0 + hl, b = n0 + bl;
                float pg = Ps[0 * 512 + hl * 32 + bl] + xzv[q][0] + bg[h];
                float pi = Ps[1 * 512 + hl * 32 + bl] + xzv[q][1] + bi[h];
                float po = Ps[2 * 512 + hl * 32 + bl] + xzv[q][2] + bo[h];
                float g  = tanhf(pg);
                float si = 1.0f / (1.0f + expf(-pi));
                float so = 1.0f / (1.0f + expf(-po));
                float c  = g * si;
                float hv = tanhf(c) * so;
                __nv_bfloat16 chh = __float2bfloat16(c);
                Wch[(size_t)h * BB + b] = chh;
                Wcl[(size_t)h * BB + b] = __float2bfloat16(c - __bfloat162float(chh));
                Hs[bl * 16 + hl] = hv;
            }
        }
        __syncthreads();

        // coalesced out writes (h-fastest through the smem bounce tile)
        for (int j = tid; j < 512; j += 384) {
            int hI = j & 15, bI = j >> 4;
            out[(size_t)t * BB * HH + (size_t)(n0 + bI) * HH + h0 + hI] = Hs[bI * 16 + hI];
        }

        grid_bar();   // all carry writes visible before next step's cp.async reads
    }
}

// ---------------------------------------------------------------------------
// kernel_launch — graph-capturable; 4 kernel nodes total
// ---------------------------------------------------------------------------
extern "C" void kernel_launch(void* const* d_in, const int* in_sizes, int n_in,
                              void* d_out, int out_size)
{
    const float* embeds = (const float*)d_in[0];
    const float* Wgx = (const float*)d_in[1];
    const float* Wgh = (const float*)d_in[2];
    const float* bg  = (const float*)d_in[3];
    const float* Wix = (const float*)d_in[4];
    const float* Wih = (const float*)d_in[5];
    const float* bi  = (const float*)d_in[6];
    // d_in[7..9] = Wfx, Wfh, bf — dead in the reference (f gate multiplied by 0)
    const float* Wox = (const float*)d_in[10];
    const float* Woh = (const float*)d_in[11];
    const float* bo  = (const float*)d_in[12];
    float* out = (float*)d_out;

    float *p_xz;
    __nv_bfloat16 *p_xt_hi, *p_xt_lo, *p_wx_hi, *p_wx_lo, *p_wh_hi, *p_wh_lo, *p_c_hi, *p_c_lo;
    cudaGetSymbolAddress((void**)&p_xz,    g_xz);
    cudaGetSymbolAddress((void**)&p_xt_hi, g_xt_hi);
    cudaGetSymbolAddress((void**)&p_xt_lo, g_xt_lo);
    cudaGetSymbolAddress((void**)&p_wx_hi, g_wx_hi);
    cudaGetSymbolAddress((void**)&p_wx_lo, g_wx_lo);
    cudaGetSymbolAddress((void**)&p_wh_hi, g_wh_hi);
    cudaGetSymbolAddress((void**)&p_wh_lo, g_wh_lo);
    cudaGetSymbolAddress((void**)&p_c_hi,  g_c_hi);
    cudaGetSymbolAddress((void**)&p_c_lo,  g_c_lo);

    cudaFuncSetAttribute(recurrence_kernel,
                         cudaFuncAttributeMaxDynamicSharedMemorySize, SMEM_REC_BYTES);

    // 1) split all 6 weight matrices into bf16 hi/lo (one launch)
    {
        long total = 3L * HH * EE + 3L * HH * HH;   // 4,718,592
        split6_kernel<<<(unsigned)((total + 255) / 256), 256>>>(
            Wgx, Wix, Wox, Wgh, Wih, Woh, p_wx_hi, p_wx_lo, p_wh_hi, p_wh_lo);
    }

    // 2) transpose+split embeds to [T][E][B]
    {
        long n = (long)TT * EE * BB;
        transpose_split_kernel<<<(unsigned)((n + 255) / 256), 256>>>(embeds, p_xt_hi, p_xt_lo);
    }

    // 3) input projections: XZ[t][3H][B] (bias added at combine)
    {
        dim3 grid(G3 / 32, TT);     // (96, 512)
        gemm_split_kernel<<<grid, 64>>>(p_wx_hi, p_wx_lo, p_xt_hi, p_xt_lo, p_xz, EE);
    }

    // 4) persistent recurrence: ONE kernel for all 512 steps
    recurrence_kernel<<<NCTA_REC, 384, SMEM_REC_BYTES>>>(
        p_wh_hi, p_wh_lo, p_xz, bg, bi, bo, p_c_hi, p_c_lo, out);
}

// round 17
// speedup vs baseline: 1.2577x; 1.2577x over previous
#include <cuda_runtime.h>
#include <cuda_bf16.h>
#include <cuda_pipeline.h>
#include <mma.h>

using namespace nvcuda;

// Problem constants
#define TT 512
#define BB 64
#define EE 512
#define HH 1024
#define G3 3072      // 3 gates * H, gate order: g, i, o
#define NCTA_REC 128 // persistent recurrence grid (64 h-tiles x 2 n-halves)

// ---- recurrence smem geometry
#define WS_LD 1032   // padded K stride for weight smem (conflict-free ldmatrix)
#define BS_LD 32     // carry smem batch stride (2-way LDSM conflict accepted)
#define NBUF 3       // carry staging buffers (prefetch depth 2)
#define SMEM_WS (48 * WS_LD)
#define SMEM_REC_BYTES (198144 + 24576 + 6144)   // 228864 <= 227KB limit

// ---- phase-1 GEMM geometry (128x64 tile, 32-K chunks, 3 buffers)
#define P1_ALD 40    // A smem k-stride (80B rows: conflict-free ldmatrix)
#define P1_BLD 72    // B smem b-stride (144B rows: conflict-free ldmatrix)
#define P1_AS_ELEM (3 * 2 * 128 * P1_ALD)   // 30720
#define P1_BS_ELEM (3 * 2 * 32 * P1_BLD)    // 13824
#define P1_SMEM_BYTES ((P1_AS_ELEM + P1_BS_ELEM) * 2)   // 89088

// ---------------------------------------------------------------------------
// Static device scratch (allocation-free rule: __device__ globals)
// ---------------------------------------------------------------------------
__device__ __align__(16) float         g_xz[(size_t)TT * G3 * BB];       // preactivations [T][3H][B]
__device__ __align__(16) __nv_bfloat16 g_xt_hi[(size_t)TT * EE * BB];    // embeds transposed [T][E][B]
__device__ __align__(16) __nv_bfloat16 g_xt_lo[(size_t)TT * EE * BB];
__device__ __align__(16) __nv_bfloat16 g_wx_hi[(size_t)G3 * EE];         // [3H][E] gate-major
__device__ __align__(16) __nv_bfloat16 g_wx_lo[(size_t)G3 * EE];
__device__ __align__(16) __nv_bfloat16 g_wh_hi[(size_t)G3 * HH];         // [3H][H] gate-major
__device__ __align__(16) __nv_bfloat16 g_wh_lo[(size_t)G3 * HH];
__device__ __align__(16) __nv_bfloat16 g_c_hi[2][(size_t)HH * BB];       // ping-pong carry c (bf16 hi/lo)
__device__ __align__(16) __nv_bfloat16 g_c_lo[2][(size_t)HH * BB];

// grid-barrier state — EXACT R12-proven protocol (zero-initialized; g_bar_cnt
// returns to 0 after every barrier, g_bar_gen monotonic across replays)
__device__ unsigned g_bar_cnt;
__device__ unsigned g_bar_gen;

// ---------------------------------------------------------------------------
// Device-wide sense-reversing barrier (all NCTA_REC CTAs co-resident, 1/SM)
// Byte-for-byte the R12 barrier that passed 4 rounds.
// ---------------------------------------------------------------------------
__device__ __forceinline__ void grid_bar()
{
    __syncthreads();
    if (threadIdx.x == 0) {
        __threadfence();                                   // release our c writes
        unsigned gen = atomicAdd(&g_bar_gen, 0u);          // read current generation
        __threadfence();                                   // order gen-read before cnt-inc
        if (atomicAdd(&g_bar_cnt, 1u) == NCTA_REC - 1u) {
            atomicExch(&g_bar_cnt, 0u);
            __threadfence();
            atomicAdd(&g_bar_gen, 1u);                     // release everyone
        } else {
            while (atomicAdd(&g_bar_gen, 0u) == gen) __nanosleep(64);
        }
        __threadfence();                                   // acquire others' c writes
    }
    __syncthreads();
}

// ---------------------------------------------------------------------------
// Fused split: all 6 weight matrices fp32 -> bf16 hi/lo, gate-major [g; i; o]
// ---------------------------------------------------------------------------
__global__ void split6_kernel(const float* __restrict__ Wgx, const float* __restrict__ Wix,
                              const float* __restrict__ Wox, const float* __restrict__ Wgh,
                              const float* __restrict__ Wih, const float* __restrict__ Woh,
                              __nv_bfloat16* __restrict__ wx_hi, __nv_bfloat16* __restrict__ wx_lo,
                              __nv_bfloat16* __restrict__ wh_hi, __nv_bfloat16* __restrict__ wh_lo)
{
    long i = (long)blockIdx.x * blockDim.x + threadIdx.x;
    const long nWx = (long)HH * EE, nWh = (long)HH * HH;
    float v;
    __nv_bfloat16 *hi, *lo;
    long idx;
    if (i < 3 * nWx) {
        int g = (int)(i / nWx);
        long j = i - (long)g * nWx;
        const float* src = (g == 0) ? Wgx : (g == 1) ? Wix : Wox;
        v = src[j]; hi = wx_hi; lo = wx_lo; idx = i;
    } else {
        long k = i - 3 * nWx;
        if (k >= 3 * nWh) return;
        int g = (int)(k / nWh);
        long j = k - (long)g * nWh;
        const float* src = (g == 0) ? Wgh : (g == 1) ? Wih : Woh;
        v = src[j]; hi = wh_hi; lo = wh_lo; idx = k;
    }
    __nv_bfloat16 h = __float2bfloat16(v);
    hi[idx] = h;
    lo[idx] = __float2bfloat16(v - __bfloat162float(h));
}

// embeds [T][B][E] -> transposed split [T][E][B]
__global__ void transpose_split_kernel(const float* __restrict__ emb,
                                       __nv_bfloat16* __restrict__ hi,
                                       __nv_bfloat16* __restrict__ lo)
{
    long i = (long)blockIdx.x * blockDim.x + threadIdx.x;   // over T*E*B
    if (i < (long)TT * EE * BB) {
        int  b  = (int)(i & (BB - 1));
        long te = i >> 6;
        int  e  = (int)(te & (EE - 1));
        int  t  = (int)(te >> 9);
        float v = emb[((long)t * BB + b) * EE + e];
        __nv_bfloat16 h = __float2bfloat16(v);
        hi[i] = h;
        lo[i] = __float2bfloat16(v - __bfloat162float(h));
    }
}

// ---------------------------------------------------------------------------
// Phase 1: XZ[t] = Wx[3072,512] * X[t][512,64].  128x64 tile, 8 warps,
// 3-buffer cp.async over 32-K chunks, one __syncthreads per chunk,
// conflict-free ldmatrix pads. blockIdx = (m-tile 0..23, t 0..511).
// ---------------------------------------------------------------------------
__global__ __launch_bounds__(256)
void gemm_xz_kernel(const __nv_bfloat16* __restrict__ Ah_g,
                    const __nv_bfloat16* __restrict__ Al_g,
                    const __nv_bfloat16* __restrict__ Bh_g,
                    const __nv_bfloat16* __restrict__ Bl_g,
                    float* __restrict__ C_base)
{
    extern __shared__ __align__(128) __nv_bfloat16 p1s[];
    __nv_bfloat16* As = p1s;                    // [3buf][2 mat][128][P1_ALD]
    __nv_bfloat16* Bs = p1s + P1_AS_ELEM;       // [3buf][2 mat][32][P1_BLD]

    const int m0 = blockIdx.x * 128;
    const long t = blockIdx.y;
    const __nv_bfloat16* Bh = Bh_g + t * EE * BB;
    const __nv_bfloat16* Bl = Bl_g + t * EE * BB;
    float* C = C_base + t * (long)G3 * BB;

    const int tid  = threadIdx.x;
    const int warp = tid >> 5;                  // 0..7, rows m0 + warp*16

    auto stage = [&](int kc, int buf) {
        // A: 128 rows x 32 k, hi+lo (1024 x 16B)
        for (int u = tid; u < 1024; u += 256) {
            int m  = u >> 9;
            int v  = u & 511;
            int r  = v >> 2;                    // 0..127
            int c8 = (v & 3) * 8;
            const __nv_bfloat16* src = (m ? Al_g : Ah_g) + (size_t)(m0 + r) * EE + kc + c8;
            __pipeline_memcpy_async(&As[((buf * 2 + m) * 128 + r) * P1_ALD + c8], src, 16);
        }
        // B: 32 k rows x 64 b, hi+lo (512 x 16B)
        for (int u = tid; u < 512; u += 256) {
            int m  = u >> 8;
            int v  = u & 255;
            int r  = v >> 3;                    // 0..31
            int c8 = (v & 7) * 8;
            const __nv_bfloat16* src = (m ? Bl : Bh) + (size_t)(kc + r) * BB + c8;
            __pipeline_memcpy_async(&Bs[((buf * 2 + m) * 32 + r) * P1_BLD + c8], src, 16);
        }
    };

    wmma::fragment<wmma::accumulator, 16, 16, 16, float> acc[4];
#pragma unroll
    for (int i = 0; i < 4; i++) wmma::fill_fragment(acc[i], 0.0f);

    stage(0, 0);  __pipeline_commit();
    stage(32, 1); __pipeline_commit();

    for (int kci = 0; kci < 16; kci++) {
        const int buf = kci % 3;
        // Drain chunk kci. Outstanding = {kci, kci+1} except at the tail where
        // only {15} remains -> must fully drain.
        if (kci == 15) __pipeline_wait_prior(0);
        else           __pipeline_wait_prior(1);
        __syncthreads();                        // publish chunk kci; MMA(kci-1) done
        if (kci + 2 < 16) {
            stage((kci + 2) * 32, (kci + 2) % 3);
            __pipeline_commit();
        }
#pragma unroll
        for (int kk = 0; kk < 2; kk++) {
            wmma::fragment<wmma::matrix_a, 16, 16, 16, __nv_bfloat16, wmma::row_major> a_hi, a_lo;
            wmma::load_matrix_sync(a_hi, &As[((buf * 2 + 0) * 128 + warp * 16) * P1_ALD + kk * 16], P1_ALD);
            wmma::load_matrix_sync(a_lo, &As[((buf * 2 + 1) * 128 + warp * 16) * P1_ALD + kk * 16], P1_ALD);
#pragma unroll
            for (int nf = 0; nf < 4; nf++) {
                wmma::fragment<wmma::matrix_b, 16, 16, 16, __nv_bfloat16, wmma::row_major> b_hi, b_lo;
                wmma::load_matrix_sync(b_hi, &Bs[((buf * 2 + 0) * 32 + kk * 16) * P1_BLD + nf * 16], P1_BLD);
                wmma::load_matrix_sync(b_lo, &Bs[((buf * 2 + 1) * 32 + kk * 16) * P1_BLD + nf * 16], P1_BLD);
                wmma::mma_sync(acc[nf], a_hi, b_hi, acc[nf]);
                wmma::mma_sync(acc[nf], a_hi, b_lo, acc[nf]);
                wmma::mma_sync(acc[nf], a_lo, b_hi, acc[nf]);
            }
        }
    }

#pragma unroll
    for (int nf = 0; nf < 4; nf++)
        wmma::store_matrix_sync(&C[(size_t)(m0 + warp * 16) * 64 + nf * 16],
                                acc[nf], 64, wmma::mem_row_major);
}

// ---------------------------------------------------------------------------
// Phase 2: persistent recurrence. 128 CTAs x 384 threads (12 warps).
// Identical to the R12-passing structure + tail drain; R12-proven barrier.
// ---------------------------------------------------------------------------
__global__ __launch_bounds__(384)
void recurrence_kernel(const __nv_bfloat16* __restrict__ Wh_hi,
                       const __nv_bfloat16* __restrict__ Wh_lo,
                       const float* __restrict__ xz,
                       const float* __restrict__ bg,
                       const float* __restrict__ bi,
                       const float* __restrict__ bo,
                       __nv_bfloat16* __restrict__ c_hi,   // [2][H*B]
                       __nv_bfloat16* __restrict__ c_lo,   // [2][H*B]
                       float* __restrict__ out)
{
    extern __shared__ __align__(128) char smem_raw[];
    __nv_bfloat16* ws_hi = (__nv_bfloat16*)smem_raw;        // [48][WS_LD]
    __nv_bfloat16* ws_lo = ws_hi + SMEM_WS;
    __nv_bfloat16* bs    = ws_lo + SMEM_WS;                 // [NBUF][2 mat][64][BS_LD]
    float* Ps = (float*)(bs + NBUF * 2 * 64 * BS_LD);       // [3][16][32]
    float* Hs = (float*)bs;                                  // alias: free at combine time

    const int cta   = blockIdx.x;
    const int h0    = (cta >> 1) * 16;
    const int n0    = (cta & 1) * 32;
    const int tid   = threadIdx.x;
    const int warp  = tid >> 5;           // 0..11
    const int nf    = warp & 1;
    const int khalf = (warp >> 1) & 1;
    const int gate  = warp >> 2;

    // ---- one-time: preload this CTA's 48x1024 hi/lo weight rows into smem
    for (int u = tid; u < 2 * 48 * 128; u += 384) {
        int m  = (u >= 6144);
        int v  = m ? u - 6144 : u;
        int r  = v >> 7;
        int c8 = (v & 127) * 8;
        int g  = r >> 4, hl = r & 15;
        const __nv_bfloat16* src = (m ? Wh_lo : Wh_hi) + (size_t)(g * HH + h0 + hl) * HH + c8;
        __nv_bfloat16* dst = (m ? ws_lo : ws_hi) + r * WS_LD + c8;
        *(uint4*)dst = *(const uint4*)src;
    }

    // ---- one-time: zero owned slice of carry buffer 0
    for (int u = tid; u < 512; u += 384) {
        int hl = u >> 5, bl = u & 31;
        size_t off = (size_t)(h0 + hl) * BB + n0 + bl;
        c_hi[off] = __float2bfloat16(0.0f);
        c_lo[off] = __float2bfloat16(0.0f);
    }
    grid_bar();   // also publishes smem weight preload (via its __syncthreads)

    auto stage = [&](const __nv_bfloat16* Ch, const __nv_bfloat16* Cl, int kc, int buf) {
        __nv_bfloat16* bh  = bs + (buf * 2 + 0) * 64 * BS_LD;
        __nv_bfloat16* blo = bs + (buf * 2 + 1) * 64 * BS_LD;
        for (int u = tid; u < 512; u += 384) {
            int m  = u >> 8;
            int v  = u & 255;
            int r  = v >> 2;
            int c8 = (v & 3) * 8;
            const __nv_bfloat16* src = (m ? Cl : Ch) + (size_t)(kc + r) * BB + n0 + c8;
            __nv_bfloat16* dst = (m ? blo : bh) + r * BS_LD + c8;
            __pipeline_memcpy_async(dst, src, 16);   // cp.async.cg (L1 bypass)
        }
    };

    const __nv_bfloat16* arow_hi = ws_hi + gate * 16 * WS_LD;
    const __nv_bfloat16* arow_lo = ws_lo + gate * 16 * WS_LD;

    const int i0 = tid, i1 = tid + 384;

    for (int t = 0; t < TT; t++) {
        const int rb = t & 1;
        const __nv_bfloat16* Ch = c_hi + (size_t)rb * HH * BB;
        const __nv_bfloat16* Cl = c_lo + (size_t)rb * HH * BB;
        __nv_bfloat16* Wch = c_hi + (size_t)(rb ^ 1) * HH * BB;
        __nv_bfloat16* Wcl = c_lo + (size_t)(rb ^ 1) * HH * BB;
        const float* xzt = xz + (size_t)t * G3 * BB;

        // prefetch xz operands for this thread's combine positions
        float xzv[2][3];
        {
            int hl = i0 >> 5, bl = i0 & 31;
            int h = h0 + hl, b = n0 + bl;
#pragma unroll
            for (int g = 0; g < 3; g++)
                xzv[0][g] = __ldcg(&xzt[(size_t)(g * HH + h) * BB + b]);
            if (i1 < 512) {
                int hl1 = i1 >> 5, bl1 = i1 & 31;
                int h1 = h0 + hl1, b1 = n0 + bl1;
#pragma unroll
                for (int g = 0; g < 3; g++)
                    xzv[1][g] = __ldcg(&xzt[(size_t)(g * HH + h1) * BB + b1]);
            }
        }

        wmma::fragment<wmma::accumulator, 16, 16, 16, float> acc0, acc1, acc2;
        wmma::fill_fragment(acc0, 0.0f);
        wmma::fill_fragment(acc1, 0.0f);
        wmma::fill_fragment(acc2, 0.0f);

        stage(Ch, Cl, 0, 0);  __pipeline_commit();
        stage(Ch, Cl, 64, 1); __pipeline_commit();

        for (int kci = 0; kci < 16; kci++) {
            const int buf = kci % NBUF;
            // Full drain at the tail
            if (kci == 15) __pipeline_wait_prior(0);
            else           __pipeline_wait_prior(1);
            __syncthreads();
            if (kci + 2 < 16) {
                stage(Ch, Cl, (kci + 2) * 64, (kci + 2) % NBUF);
                __pipeline_commit();
            }

            const __nv_bfloat16* bhp = bs + (buf * 2 + 0) * 64 * BS_LD + nf * 16;
            const __nv_bfloat16* blp = bs + (buf * 2 + 1) * 64 * BS_LD + nf * 16;
#pragma unroll
            for (int j = 0; j < 2; j++) {
                const int kk = khalf * 2 + j;
                wmma::fragment<wmma::matrix_a, 16, 16, 16, __nv_bfloat16, wmma::row_major> a_hi, a_lo;
                wmma::load_matrix_sync(a_hi, arow_hi + kci * 64 + kk * 16, WS_LD);
                wmma::load_matrix_sync(a_lo, arow_lo + kci * 64 + kk * 16, WS_LD);
                wmma::fragment<wmma::matrix_b, 16, 16, 16, __nv_bfloat16, wmma::row_major> b_hi, b_lo;
                wmma::load_matrix_sync(b_hi, bhp + kk * 16 * BS_LD, BS_LD);
                wmma::load_matrix_sync(b_lo, blp + kk * 16 * BS_LD, BS_LD);
                wmma::mma_sync(acc0, a_hi, b_hi, acc0);
                wmma::mma_sync(acc1, a_hi, b_lo, acc1);
                wmma::mma_sync(acc2, a_lo, b_hi, acc2);
            }
        }

#pragma unroll
        for (int e = 0; e < acc0.num_elements; e++)
            acc0.x[e] += acc1.x[e] + acc2.x[e];

        // merge k-halves via Ps
        __syncthreads();
        if (khalf == 1)
            wmma::store_matrix_sync(Ps + gate * 512 + nf * 16, acc0, 32, wmma::mem_row_major);
        __syncthreads();
        if (khalf == 0) {
            wmma::fragment<wmma::accumulator, 16, 16, 16, float> accP;
            wmma::load_matrix_sync(accP, Ps + gate * 512 + nf * 16, 32, wmma::mem_row_major);
#pragma unroll
            for (int e = 0; e < acc0.num_elements; e++)
                acc0.x[e] += accP.x[e];
            wmma::store_matrix_sync(Ps + gate * 512 + nf * 16, acc0, 32, wmma::mem_row_major);
        }
        __syncthreads();

        // combine
#pragma unroll
        for (int q = 0; q < 2; q++) {
            int i = (q == 0) ? i0 : i1;
            if (i < 512) {
                int hl = i >> 5, bl = i & 31;
                int h = h0 + hl, b = n0 + bl;
                float pg = Ps[0 * 512 + hl * 32 + bl] + xzv[q][0] + bg[h];
                float pi = Ps[1 * 512 + hl * 32 + bl] + xzv[q][1] + bi[h];
                float po = Ps[2 * 512 + hl * 32 + bl] + xzv[q][2] + bo[h];
                float g  = tanhf(pg);
                float si = 1.0f / (1.0f + expf(-pi));
                float so = 1.0f / (1.0f + expf(-po));
                float c  = g * si;
                float hv = tanhf(c) * so;
                __nv_bfloat16 chh = __float2bfloat16(c);
                Wch[(size_t)h * BB + b] = chh;
                Wcl[(size_t)h * BB + b] = __float2bfloat16(c - __bfloat162float(chh));
                Hs[bl * 16 + hl] = hv;
            }
        }
        __syncthreads();

        // coalesced out writes
        for (int j = tid; j < 512; j += 384) {
            int hI = j & 15, bI = j >> 4;
            out[(size_t)t * BB * HH + (size_t)(n0 + bI) * HH + h0 + hI] = Hs[bI * 16 + hI];
        }

        grid_bar();
    }
}

// ---------------------------------------------------------------------------
// kernel_launch — graph-capturable; 4 kernel nodes total
// ---------------------------------------------------------------------------
extern "C" void kernel_launch(void* const* d_in, const int* in_sizes, int n_in,
                              void* d_out, int out_size)
{
    const float* embeds = (const float*)d_in[0];
    const float* Wgx = (const float*)d_in[1];
    const float* Wgh = (const float*)d_in[2];
    const float* bg  = (const float*)d_in[3];
    const float* Wix = (const float*)d_in[4];
    const float* Wih = (const float*)d_in[5];
    const float* bi  = (const float*)d_in[6];
    // d_in[7..9] = Wfx, Wfh, bf — dead in the reference (f gate multiplied by 0)
    const float* Wox = (const float*)d_in[10];
    const float* Woh = (const float*)d_in[11];
    const float* bo  = (const float*)d_in[12];
    float* out = (float*)d_out;

    float *p_xz;
    __nv_bfloat16 *p_xt_hi, *p_xt_lo, *p_wx_hi, *p_wx_lo, *p_wh_hi, *p_wh_lo, *p_c_hi, *p_c_lo;
    cudaGetSymbolAddress((void**)&p_xz,    g_xz);
    cudaGetSymbolAddress((void**)&p_xt_hi, g_xt_hi);
    cudaGetSymbolAddress((void**)&p_xt_lo, g_xt_lo);
    cudaGetSymbolAddress((void**)&p_wx_hi, g_wx_hi);
    cudaGetSymbolAddress((void**)&p_wx_lo, g_wx_lo);
    cudaGetSymbolAddress((void**)&p_wh_hi, g_wh_hi);
    cudaGetSymbolAddress((void**)&p_wh_lo, g_wh_lo);
    cudaGetSymbolAddress((void**)&p_c_hi,  g_c_hi);
    cudaGetSymbolAddress((void**)&p_c_lo,  g_c_lo);

    cudaFuncSetAttribute(recurrence_kernel,
                         cudaFuncAttributeMaxDynamicSharedMemorySize, SMEM_REC_BYTES);
    cudaFuncSetAttribute(gemm_xz_kernel,
                         cudaFuncAttributeMaxDynamicSharedMemorySize, P1_SMEM_BYTES);

    // 1) split all 6 weight matrices into bf16 hi/lo (one launch)
    {
        long total = 3L * HH * EE + 3L * HH * HH;   // 4,718,592
        split6_kernel<<<(unsigned)((total + 255) / 256), 256>>>(
            Wgx, Wix, Wox, Wgh, Wih, Woh, p_wx_hi, p_wx_lo, p_wh_hi, p_wh_lo);
    }

    // 2) transpose+split embeds to [T][E][B]
    {
        long n = (long)TT * EE * BB;
        transpose_split_kernel<<<(unsigned)((n + 255) / 256), 256>>>(embeds, p_xt_hi, p_xt_lo);
    }

    // 3) input projections: XZ[t][3H][B] (bias added at combine)
    {
        dim3 grid(G3 / 128, TT);    // (24, 512)
        gemm_xz_kernel<<<grid, 256, P1_SMEM_BYTES>>>(p_wx_hi, p_wx_lo, p_xt_hi, p_xt_lo, p_xz);
    }

    // 4) persistent recurrence: ONE kernel for all 512 steps
    recurrence_kernel<<<NCTA_REC, 384, SMEM_REC_BYTES>>>(
        p_wh_hi, p_wh_lo, p_xz, bg, bi, bo, p_c_hi, p_c_lo, out);
}